// round 7
// baseline (speedup 1.0000x reference)
#include <cuda_runtime.h>

#define NR      96
#define DIM     768
#define TRIU    4560
#define P_CNT   9120
#define Q_CNT   9216
#define THR     0.3f
#define SPLITK  4              // 768/4 = 192 per split
#define NEG_SL  48
#define NEG_PER 192
#define POS_GR  3
#define RPOS    6
#define HTHR    512
#define HB      (NEG_SL * POS_GR)   // 144

// ---------------- device scratch ----------------
__device__ float g_partPos[SPLITK * P_CNT];
__device__ float g_partNeg[SPLITK * Q_CNT];
__device__ float g_partDiag[SPLITK * 2 * NR];
__device__ float g_blockSum[HB];
__device__ float g_posSum[POS_GR];
__device__ float g_negSum[NEG_SL];
__device__ unsigned g_count = 0;

// ---------------- helpers ----------------
__device__ __forceinline__ unsigned long long addx2(unsigned long long a,
                                                    unsigned long long b) {
    unsigned long long r;
    asm("add.rn.f32x2 %0, %1, %2;" : "=l"(r) : "l"(a), "l"(b));
    return r;
}
#define ABSMASK 0x7fffffff7fffffffULL

__device__ __forceinline__ int triu_base(int i) { return i * (191 - i) / 2; }
__device__ __forceinline__ int triu_idx(int i, int j) {
    return triu_base(i) + (j - i - 1);
}

__device__ __forceinline__ float blockReduce512(float v, float* sbuf16) {
    __syncthreads();
    int t = threadIdx.x;
    #pragma unroll
    for (int o = 16; o; o >>= 1) v += __shfl_down_sync(0xffffffffu, v, o);
    if ((t & 31) == 0) sbuf16[t >> 5] = v;
    __syncthreads();
    float r = 0.f;
    if (t < 16) {
        r = sbuf16[t];
        #pragma unroll
        for (int o = 8; o; o >>= 1) r += __shfl_down_sync(0xffffu, r, o);
    }
    return r;   // valid at t == 0
}

// ---------------- K1: RAW grams + diag partials (84 blocks x 256) ---------
__global__ void __launch_bounds__(256) k_gram(const float* __restrict__ S,
                                              const float* __restrict__ A) {
    __shared__ float As[32][34];
    __shared__ float Bs[32][34];

    int bx = blockIdx.x;
    int sk = bx / 21;
    int tl = bx % 21;

    int m, tr, tc;
    if (tl < 9) { m = 0; tr = tl / 3; tc = tl % 3; }
    else {
        int q = tl - 9;
        m = 1 + q / 6;
        const int TR6[6] = {0,0,0,1,1,2};
        const int TC6[6] = {0,1,2,1,2,2};
        tr = TR6[q % 6]; tc = TC6[q % 6];
    }
    // m0: neg = A x S^T; m1: S x S^T; m2: A x A^T
    const float* Ap = (m == 1) ? S : A;
    const float* Bp = (m == 2) ? A : S;

    int t  = threadIdx.x;
    int tx = t & 15, ty = t >> 4;

    float acc00 = 0.f, acc01 = 0.f, acc10 = 0.f, acc11 = 0.f;

    for (int ch = 0; ch < 6; ch++) {
        int kb = sk * 192 + ch * 32;
        __syncthreads();
        #pragma unroll
        for (int p = 0; p < 4; p++) {
            int lin = t + p * 256;
            int kk  = lin & 31, row = lin >> 5;
            As[kk][row] = Ap[(tr * 32 + row) * DIM + kb + kk];
            Bs[kk][row] = Bp[(tc * 32 + row) * DIM + kb + kk];
        }
        __syncthreads();
        #pragma unroll
        for (int kk = 0; kk < 32; kk++) {
            float2 a = *(const float2*)&As[kk][2 * ty];
            float2 b = *(const float2*)&Bs[kk][2 * tx];
            acc00 += a.x * b.x; acc01 += a.x * b.y;
            acc10 += a.y * b.x; acc11 += a.y * b.y;
        }
    }

    int r0 = tr * 32 + 2 * ty;
    int c0 = tc * 32 + 2 * tx;
    if (m == 0) {
        float* dst = g_partNeg + sk * Q_CNT;
        dst[r0 * 96 + c0]           = acc00;
        dst[r0 * 96 + c0 + 1]       = acc01;
        dst[(r0 + 1) * 96 + c0]     = acc10;
        dst[(r0 + 1) * 96 + c0 + 1] = acc11;
    } else {
        float* dst = g_partPos + sk * P_CNT + ((m == 2) ? TRIU : 0);
        if (r0     < c0    ) dst[triu_idx(r0,     c0    )] = acc00;
        if (r0     < c0 + 1) dst[triu_idx(r0,     c0 + 1)] = acc01;
        if (r0 + 1 < c0    ) dst[triu_idx(r0 + 1, c0    )] = acc10;
        if (r0 + 1 < c0 + 1) dst[triu_idx(r0 + 1, c0 + 1)] = acc11;
        if (r0 == c0) {  // diagonal entries -> squared row norms
            int off = (m == 1) ? 0 : NR;
            g_partDiag[sk * 2 * NR + off + r0]     = acc00;
            g_partDiag[sk * 2 * NR + off + r0 + 1] = acc11;
        }
    }
}

// ---------------- K2: normalize + hinge + fused final (144 x 512) ---------
__global__ void __launch_bounds__(HTHR, 1) k_hinge(float* __restrict__ out) {
    __shared__ __align__(16) float s_neg[NEG_PER];
    __shared__ float s_inv[2 * NR];
    __shared__ float sbuf[16];
    __shared__ bool s_last;

    int bid = blockIdx.x;
    int ns  = bid / POS_GR;       // 0..47
    int pg  = bid % POS_GR;       // 0..2
    int t   = threadIdx.x;

    // --- combine diag partials -> inverse norms
    if (t < 2 * NR) {
        float d = ((g_partDiag[0 * 192 + t] + g_partDiag[1 * 192 + t]) +
                   (g_partDiag[2 * 192 + t] + g_partDiag[3 * 192 + t]));
        s_inv[t] = 1.0f / fmaxf(sqrtf(d), 1e-8f);
    }
    __syncthreads();

    // --- combine + normalize this block's neg slice into smem (+THR folded)
    int j0 = ns * NEG_PER;
    if (t < NEG_PER) {
        int gj = j0 + t;
        float raw = ((g_partNeg[0 * Q_CNT + gj] + g_partNeg[1 * Q_CNT + gj]) +
                     (g_partNeg[2 * Q_CNT + gj] + g_partNeg[3 * Q_CNT + gj]));
        int r = gj / 96, c = gj % 96;
        s_neg[t] = raw * s_inv[NR + r] * s_inv[c] + THR;
    }

    // --- combine + normalize this thread's RPOS pos values
    float posv[RPOS];
    unsigned long long c2[RPOS];
    bool act[RPOS];
    #pragma unroll
    for (int rr = 0; rr < RPOS; rr++) {
        int pid = pg * (HTHR * RPOS) + rr * HTHR + t;
        act[rr] = (pid < P_CNT);
        posv[rr] = 0.f;
        if (act[rr]) {
            float raw = ((g_partPos[0 * P_CNT + pid] + g_partPos[1 * P_CNT + pid]) +
                         (g_partPos[2 * P_CNT + pid] + g_partPos[3 * P_CNT + pid]));
            int invo = (pid < TRIU) ? 0 : NR;
            int p    = (pid < TRIU) ? pid : (pid - TRIU);
            // 36481 - 8p is exact in fp32 (< 2^24); sqrtf error <= 1 index, fixed up
            int i = (int)((191.0f - sqrtf((float)(36481 - 8 * p))) * 0.5f);
            while (triu_base(i + 1) <= p) ++i;
            while (triu_base(i) > p)      --i;
            int j = p - triu_base(i) + i + 1;
            posv[rr] = raw * s_inv[invo + i] * s_inv[invo + j];
        }
        unsigned cu = __float_as_uint(-posv[rr]);
        c2[rr] = ((unsigned long long)cu << 32) | cu;
    }
    __syncthreads();

    // --- designated blocks record separable sums
    if (ns == 0) {
        float ps = 0.f;
        #pragma unroll
        for (int rr = 0; rr < RPOS; rr++) ps += act[rr] ? posv[rr] : 0.f;
        float r = blockReduce512(ps, sbuf);
        if (t == 0) g_posSum[pg] = r;
    }
    if (pg == 0) {
        float v = (t < NEG_PER) ? (s_neg[t] - THR) : 0.f;
        float r = blockReduce512(v, sbuf);
        if (t == 0) g_negSum[ns] = r;
    }

    // --- main hinge: 6 pos chains x packed negs; 1 LDS.128 per 24 pairs
    unsigned long long acc[RPOS];
    #pragma unroll
    for (int rr = 0; rr < RPOS; rr++) acc[rr] = 0ull;

    const ulonglong2* sn = reinterpret_cast<const ulonglong2*>(s_neg); // 48
    #pragma unroll 4
    for (int i = 0; i < NEG_PER / 4; i++) {
        ulonglong2 v = sn[i];
        #pragma unroll
        for (int rr = 0; rr < RPOS; rr++)
            acc[rr] = addx2(acc[rr], addx2(v.x, c2[rr]) & ABSMASK);
        #pragma unroll
        for (int rr = 0; rr < RPOS; rr++)
            acc[rr] = addx2(acc[rr], addx2(v.y, c2[rr]) & ABSMASK);
    }

    float accf = 0.f;
    #pragma unroll
    for (int rr = 0; rr < RPOS; rr++) {
        float s = __uint_as_float((unsigned)acc[rr]) +
                  __uint_as_float((unsigned)(acc[rr] >> 32));
        accf += act[rr] ? s : 0.f;
    }
    float bsum = blockReduce512(accf, sbuf);
    if (t == 0) g_blockSum[bid] = bsum;

    // --- last-block-done deterministic final combine
    if (t == 0) {
        __threadfence();
        unsigned old = atomicInc(&g_count, HB - 1);
        s_last = (old == HB - 1);
    }
    __syncthreads();
    if (!s_last) return;
    __threadfence();

    float vA = (t < HB)     ? g_blockSum[t] : 0.f;
    float S_abs = blockReduce512(vA, sbuf);
    float vP = (t < POS_GR) ? g_posSum[t]   : 0.f;
    float S_pos = blockReduce512(vP, sbuf);
    float vN = (t < NEG_SL) ? g_negSum[t]   : 0.f;
    float S_neg = blockReduce512(vN, sbuf);

    if (t == 0) {
        const double P = (double)P_CNT, Q = (double)Q_CNT, thr = (double)THR;
        double Sx = P * (double)S_neg - Q * (double)S_pos + P * Q * thr;
        out[0] = (float)(0.5 * (Sx + (double)S_abs) / (P * Q));
    }
}

// ---------------- launch ----------------
extern "C" void kernel_launch(void* const* d_in, const int* in_sizes, int n_in,
                              void* d_out, int out_size) {
    const float* stereos  = (const float*)d_in[0];
    const float* astereos = (const float*)d_in[1];
    k_gram<<<21 * SPLITK, 256>>>(stereos, astereos);
    k_hinge<<<HB, HTHR>>>((float*)d_out);
}

// round 8
// speedup vs baseline: 1.1951x; 1.1951x over previous
#include <cuda_runtime.h>

#define NR      96
#define DIM     768
#define TRIU    4560
#define P_CNT   9120
#define Q_CNT   9216
#define THR     0.3f
#define SPLITK  8              // 768/8 = 96 per split
#define NEG_SL  48
#define NEG_PER 192
#define POS_GR  3
#define RPOS    3
#define HTHR    1024
#define HB      (NEG_SL * POS_GR)   // 144

// ---------------- device scratch ----------------
__device__ float g_partPos[SPLITK * P_CNT];
__device__ float g_partNeg[SPLITK * Q_CNT];
__device__ float g_partDiag[SPLITK * 2 * NR];
__device__ float g_blockSum[HB];
__device__ float g_posSum[POS_GR];
__device__ float g_negSum[NEG_SL];
__device__ unsigned g_count = 0;

__device__ __forceinline__ int triu_base(int i) { return i * (191 - i) / 2; }
__device__ __forceinline__ int triu_idx(int i, int j) {
    return triu_base(i) + (j - i - 1);
}

__device__ __forceinline__ float blockReduce1024(float v, float* sbuf32) {
    __syncthreads();
    int t = threadIdx.x;
    #pragma unroll
    for (int o = 16; o; o >>= 1) v += __shfl_down_sync(0xffffffffu, v, o);
    if ((t & 31) == 0) sbuf32[t >> 5] = v;
    __syncthreads();
    float r = 0.f;
    if (t < 32) {
        r = sbuf32[t];
        #pragma unroll
        for (int o = 16; o; o >>= 1) r += __shfl_down_sync(0xffffffffu, r, o);
    }
    return r;   // valid at t == 0
}

// ---------------- K1: RAW grams + diag partials (168 blocks x 256) --------
__global__ void __launch_bounds__(256) k_gram(const float* __restrict__ S,
                                              const float* __restrict__ A) {
    __shared__ float As[32][34];
    __shared__ float Bs[32][34];

    int bx = blockIdx.x;
    int sk = bx / 21;
    int tl = bx % 21;

    int m, tr, tc;
    if (tl < 9) { m = 0; tr = tl / 3; tc = tl % 3; }
    else {
        int q = tl - 9;
        m = 1 + q / 6;
        const int TR6[6] = {0,0,0,1,1,2};
        const int TC6[6] = {0,1,2,1,2,2};
        tr = TR6[q % 6]; tc = TC6[q % 6];
    }
    // m0: neg = A x S^T; m1: S x S^T; m2: A x A^T
    const float* Ap = (m == 1) ? S : A;
    const float* Bp = (m == 2) ? A : S;

    int t  = threadIdx.x;
    int tx = t & 15, ty = t >> 4;

    float acc00 = 0.f, acc01 = 0.f, acc10 = 0.f, acc11 = 0.f;

    for (int ch = 0; ch < 3; ch++) {
        int kb = sk * 96 + ch * 32;
        __syncthreads();
        #pragma unroll
        for (int p = 0; p < 4; p++) {
            int lin = t + p * 256;
            int kk  = lin & 31, row = lin >> 5;
            As[kk][row] = Ap[(tr * 32 + row) * DIM + kb + kk];
            Bs[kk][row] = Bp[(tc * 32 + row) * DIM + kb + kk];
        }
        __syncthreads();
        #pragma unroll
        for (int kk = 0; kk < 32; kk++) {
            float2 a = *(const float2*)&As[kk][2 * ty];
            float2 b = *(const float2*)&Bs[kk][2 * tx];
            acc00 += a.x * b.x; acc01 += a.x * b.y;
            acc10 += a.y * b.x; acc11 += a.y * b.y;
        }
    }

    int r0 = tr * 32 + 2 * ty;
    int c0 = tc * 32 + 2 * tx;
    if (m == 0) {
        float* dst = g_partNeg + sk * Q_CNT;
        dst[r0 * 96 + c0]           = acc00;
        dst[r0 * 96 + c0 + 1]       = acc01;
        dst[(r0 + 1) * 96 + c0]     = acc10;
        dst[(r0 + 1) * 96 + c0 + 1] = acc11;
    } else {
        float* dst = g_partPos + sk * P_CNT + ((m == 2) ? TRIU : 0);
        if (r0     < c0    ) dst[triu_idx(r0,     c0    )] = acc00;
        if (r0     < c0 + 1) dst[triu_idx(r0,     c0 + 1)] = acc01;
        if (r0 + 1 < c0    ) dst[triu_idx(r0 + 1, c0    )] = acc10;
        if (r0 + 1 < c0 + 1) dst[triu_idx(r0 + 1, c0 + 1)] = acc11;
        if (r0 == c0) {  // diagonal entries -> squared row norms
            int off = (m == 1) ? 0 : NR;
            g_partDiag[sk * 2 * NR + off + r0]     = acc00;
            g_partDiag[sk * 2 * NR + off + r0 + 1] = acc11;
        }
    }
}

// ---------------- K2: normalize + hinge + fused final (144 x 1024) --------
__global__ void __launch_bounds__(HTHR, 1) k_hinge(float* __restrict__ out) {
    __shared__ __align__(16) float s_neg[NEG_PER];
    __shared__ float s_inv[2 * NR];
    __shared__ float sbuf[32];
    __shared__ bool s_last;

    int bid = blockIdx.x;
    int ns  = bid / POS_GR;       // 0..47
    int pg  = bid % POS_GR;       // 0..2
    int t   = threadIdx.x;

    // --- combine diag partials -> inverse norms
    if (t < 2 * NR) {
        float d = ((g_partDiag[0 * 192 + t] + g_partDiag[1 * 192 + t]) +
                   (g_partDiag[2 * 192 + t] + g_partDiag[3 * 192 + t])) +
                  ((g_partDiag[4 * 192 + t] + g_partDiag[5 * 192 + t]) +
                   (g_partDiag[6 * 192 + t] + g_partDiag[7 * 192 + t]));
        s_inv[t] = 1.0f / fmaxf(sqrtf(d), 1e-8f);
    }
    __syncthreads();

    // --- combine + normalize this block's neg slice into smem (+THR folded)
    int j0 = ns * NEG_PER;
    if (t < NEG_PER) {
        int gj = j0 + t;
        float raw = ((g_partNeg[0 * Q_CNT + gj] + g_partNeg[1 * Q_CNT + gj]) +
                     (g_partNeg[2 * Q_CNT + gj] + g_partNeg[3 * Q_CNT + gj])) +
                    ((g_partNeg[4 * Q_CNT + gj] + g_partNeg[5 * Q_CNT + gj]) +
                     (g_partNeg[6 * Q_CNT + gj] + g_partNeg[7 * Q_CNT + gj]));
        int r = gj / 96, c = gj % 96;
        s_neg[t] = raw * s_inv[NR + r] * s_inv[c] + THR;
    }

    // --- combine + normalize this thread's RPOS pos values
    float posv[RPOS];
    float cneg[RPOS];
    bool  act[RPOS];
    #pragma unroll
    for (int rr = 0; rr < RPOS; rr++) {
        int pid = pg * (HTHR * RPOS) + rr * HTHR + t;
        act[rr] = (pid < P_CNT);
        posv[rr] = 0.f;
        if (act[rr]) {
            float raw = ((g_partPos[0 * P_CNT + pid] + g_partPos[1 * P_CNT + pid]) +
                         (g_partPos[2 * P_CNT + pid] + g_partPos[3 * P_CNT + pid])) +
                        ((g_partPos[4 * P_CNT + pid] + g_partPos[5 * P_CNT + pid]) +
                         (g_partPos[6 * P_CNT + pid] + g_partPos[7 * P_CNT + pid]));
            int invo = (pid < TRIU) ? 0 : NR;
            int p    = (pid < TRIU) ? pid : (pid - TRIU);
            // 36481 - 8p exact in fp32 (< 2^24); sqrtf off-by-one fixed below
            int i = (int)((191.0f - sqrtf((float)(36481 - 8 * p))) * 0.5f);
            while (triu_base(i + 1) <= p) ++i;
            while (triu_base(i) > p)      --i;
            int j = p - triu_base(i) + i + 1;
            posv[rr] = raw * s_inv[invo + i] * s_inv[invo + j];
        }
        cneg[rr] = -posv[rr];
    }
    __syncthreads();

    // --- designated blocks record separable sums
    if (ns == 0) {
        float ps = 0.f;
        #pragma unroll
        for (int rr = 0; rr < RPOS; rr++) ps += act[rr] ? posv[rr] : 0.f;
        float r = blockReduce1024(ps, sbuf);
        if (t == 0) g_posSum[pg] = r;
    }
    if (pg == 0) {
        float v = (t < NEG_PER) ? (s_neg[t] - THR) : 0.f;
        float r = blockReduce1024(v, sbuf);
        if (t == 0) g_negSum[ns] = r;
    }

    // --- main hinge: scalar FADD + |.| modifier; 3 pos chains x 2 accs ----
    float acc[RPOS][2];
    #pragma unroll
    for (int rr = 0; rr < RPOS; rr++) { acc[rr][0] = 0.f; acc[rr][1] = 0.f; }

    const float4* sn4 = reinterpret_cast<const float4*>(s_neg);  // 48 vecs
    #pragma unroll 4
    for (int i = 0; i < NEG_PER / 4; i++) {
        float4 v = sn4[i];
        #pragma unroll
        for (int rr = 0; rr < RPOS; rr++) {
            acc[rr][0] += fabsf(v.x + cneg[rr]);
            acc[rr][1] += fabsf(v.y + cneg[rr]);
            acc[rr][0] += fabsf(v.z + cneg[rr]);
            acc[rr][1] += fabsf(v.w + cneg[rr]);
        }
    }

    float accf = 0.f;
    #pragma unroll
    for (int rr = 0; rr < RPOS; rr++)
        accf += act[rr] ? (acc[rr][0] + acc[rr][1]) : 0.f;

    float bsum = blockReduce1024(accf, sbuf);
    if (t == 0) g_blockSum[bid] = bsum;

    // --- last-block-done deterministic final combine
    if (t == 0) {
        __threadfence();
        unsigned old = atomicInc(&g_count, HB - 1);
        s_last = (old == HB - 1);
    }
    __syncthreads();
    if (!s_last) return;
    __threadfence();

    float vA = (t < HB)     ? g_blockSum[t] : 0.f;
    float S_abs = blockReduce1024(vA, sbuf);
    float vP = (t < POS_GR) ? g_posSum[t]   : 0.f;
    float S_pos = blockReduce1024(vP, sbuf);
    float vN = (t < NEG_SL) ? g_negSum[t]   : 0.f;
    float S_neg = blockReduce1024(vN, sbuf);

    if (t == 0) {
        const double P = (double)P_CNT, Q = (double)Q_CNT, thr = (double)THR;
        double Sx = P * (double)S_neg - Q * (double)S_pos + P * Q * thr;
        out[0] = (float)(0.5 * (Sx + (double)S_abs) / (P * Q));
    }
}

// ---------------- launch ----------------
extern "C" void kernel_launch(void* const* d_in, const int* in_sizes, int n_in,
                              void* d_out, int out_size) {
    const float* stereos  = (const float*)d_in[0];
    const float* astereos = (const float*)d_in[1];
    k_gram<<<21 * SPLITK, 256>>>(stereos, astereos);
    k_hinge<<<HB, HTHR>>>((float*)d_out);
}